// round 1
// baseline (speedup 1.0000x reference)
#include <cuda_runtime.h>
#include <math.h>

// Problem constants (fixed by the dataset)
#define NMAX   50000
#define FD     128
#define GG     64

// Scratch (static __device__ — no allocation allowed)
__device__ float d_bufA[NMAX * FD];   // GEMM output / messages m
__device__ float d_bufB[NMAX * FD];   // aggregation / hidden
__device__ float d_dinv[NMAX];        // degree -> d^{-1/2}
__device__ float d_gpool[GG * FD];    // pooled graph features

// ---------------- degree / normalization ----------------
__global__ void deg_init(float* deg, int n) {
    int i = blockIdx.x * blockDim.x + threadIdx.x;
    if (i < n) deg[i] = 1.0f;                  // self loop
}

__global__ void deg_count(const int* __restrict__ dst, float* deg, int E) {
    int i = blockIdx.x * blockDim.x + threadIdx.x;
    if (i < E) atomicAdd(&deg[dst[i]], 1.0f);
}

__global__ void deg_to_dinv(float* deg, int n) {
    int i = blockIdx.x * blockDim.x + threadIdx.x;
    if (i < n) deg[i] = rsqrtf(deg[i]);        // deg >= 1 always
}

// ---------------- 50000x128 @ 128x128 fp32 GEMM ----------------
// Block: 256 threads, tile 32 rows x 128 cols, 4x4 register tile per thread.
// W (64KB) + X tile (16KB) in dynamic smem.
__global__ void gemm128(const float* __restrict__ X, const float* __restrict__ W,
                        float* __restrict__ Y, int n) {
    extern __shared__ float sh[];
    float* Wsh = sh;             // 128*128
    float* Xsh = sh + FD * FD;   // 32*128

    for (int i = threadIdx.x; i < FD * FD; i += 256) Wsh[i] = W[i];

    int tx = threadIdx.x & 31;   // column group
    int ty = threadIdx.x >> 5;   // row group (8 groups of 4 rows)
    int c0 = tx * 4;
    int r0 = ty * 4;

    for (int tile = blockIdx.x * 32; tile < n; tile += gridDim.x * 32) {
        __syncthreads();
        int rows = n - tile; if (rows > 32) rows = 32;
        for (int i = threadIdx.x; i < rows * FD; i += 256)
            Xsh[i] = X[(size_t)tile * FD + i];
        __syncthreads();

        float acc[4][4] = {};
        #pragma unroll 8
        for (int k = 0; k < FD; k++) {
            float4 wv = *(const float4*)&Wsh[k * FD + c0];
            #pragma unroll
            for (int j = 0; j < 4; j++) {
                float xv = Xsh[(r0 + j) * FD + k];
                acc[j][0] = fmaf(xv, wv.x, acc[j][0]);
                acc[j][1] = fmaf(xv, wv.y, acc[j][1]);
                acc[j][2] = fmaf(xv, wv.z, acc[j][2]);
                acc[j][3] = fmaf(xv, wv.w, acc[j][3]);
            }
        }
        #pragma unroll
        for (int j = 0; j < 4; j++) {
            int r = tile + r0 + j;
            if (r < n)
                *(float4*)&Y[(size_t)r * FD + c0] =
                    make_float4(acc[j][0], acc[j][1], acc[j][2], acc[j][3]);
        }
    }
}

// ---------------- self loop: agg = m * dinv^2 ----------------
__global__ void self_loop_init(const float* __restrict__ m, const float* __restrict__ dinv,
                               float* __restrict__ agg, int n) {
    int idx = blockIdx.x * blockDim.x + threadIdx.x;   // over n*32 float4s
    if (idx >= n * 32) return;
    int node = idx >> 5;
    float w = dinv[node]; w *= w;
    float4 v = ((const float4*)m)[idx];
    v.x *= w; v.y *= w; v.z *= w; v.w *= w;
    ((float4*)agg)[idx] = v;
}

// ---------------- edge scatter: one warp per edge ----------------
__global__ void scatter_edges(const float* __restrict__ m, const int* __restrict__ ei,
                              const float* __restrict__ dinv, float* agg, int E) {
    int gid = blockIdx.x * blockDim.x + threadIdx.x;
    int e = gid >> 5;
    if (e >= E) return;
    int lane = gid & 31;
    int s = __ldg(&ei[e]);
    int d = __ldg(&ei[E + e]);
    float w = dinv[s] * dinv[d];
    float4 v = ((const float4*)m)[(size_t)s * 32 + lane];
    float* a = agg + (size_t)d * FD + lane * 4;
    asm volatile("red.global.add.v4.f32 [%0], {%1,%2,%3,%4};"
                 :: "l"(a), "f"(v.x * w), "f"(v.y * w), "f"(v.z * w), "f"(v.w * w)
                 : "memory");
}

// ---------------- bias + relu (in place, float4) ----------------
__global__ void bias_relu(float* h, const float* __restrict__ b, int n) {
    int idx = blockIdx.x * blockDim.x + threadIdx.x;   // over n*32 float4s
    if (idx >= n * 32) return;
    int c4 = idx & 31;
    float4 v = ((float4*)h)[idx];
    float4 bb = ((const float4*)b)[c4];
    v.x = fmaxf(v.x + bb.x, 0.f);
    v.y = fmaxf(v.y + bb.y, 0.f);
    v.z = fmaxf(v.z + bb.z, 0.f);
    v.w = fmaxf(v.w + bb.w, 0.f);
    ((float4*)h)[idx] = v;
}

// ---------------- global max pool ----------------
__global__ void pool_init(float* g) {
    int i = blockIdx.x * blockDim.x + threadIdx.x;
    if (i < GG * FD) g[i] = 0.0f;              // inputs are relu outputs (>= 0)
}

__global__ void pool_max(const float* __restrict__ h, const int* __restrict__ batch,
                         float* g, int n) {
    int idx = blockIdx.x * blockDim.x + threadIdx.x;
    if (idx >= n * FD) return;
    int node = idx >> 7;
    int c = idx & 127;
    int b = __ldg(&batch[node]);
    float v = h[idx];
    atomicMax((int*)&g[b * FD + c], __float_as_int(v));  // valid: v >= 0
}

// ---------------- head: relu(g@W3+b3) @ W4 + b4, log_softmax ----------------
__global__ void head(const float* __restrict__ g, const float* __restrict__ W3,
                     const float* __restrict__ b3, const float* __restrict__ W4,
                     const float* __restrict__ b4, float* __restrict__ out) {
    __shared__ float gs[FD];
    __shared__ float red0[4], red1[4];
    int r = blockIdx.x;
    int c = threadIdx.x;
    gs[c] = g[r * FD + c];
    __syncthreads();
    float acc = b3[c];
    #pragma unroll 8
    for (int k = 0; k < FD; k++)
        acc = fmaf(gs[k], W3[k * FD + c], acc);
    float z = acc > 0.f ? acc : 0.f;
    float p0 = z * W4[c * 2 + 0];
    float p1 = z * W4[c * 2 + 1];
    #pragma unroll
    for (int o = 16; o; o >>= 1) {
        p0 += __shfl_down_sync(0xFFFFFFFFu, p0, o);
        p1 += __shfl_down_sync(0xFFFFFFFFu, p1, o);
    }
    int wid = c >> 5;
    if ((c & 31) == 0) { red0[wid] = p0; red1[wid] = p1; }
    __syncthreads();
    if (c == 0) {
        float l0 = red0[0] + red0[1] + red0[2] + red0[3] + b4[0];
        float l1 = red1[0] + red1[1] + red1[2] + red1[3] + b4[1];
        float mx = fmaxf(l0, l1);
        float lse = mx + logf(expf(l0 - mx) + expf(l1 - mx));
        out[r * 2 + 0] = l0 - lse;
        out[r * 2 + 1] = l1 - lse;
    }
}

extern "C" void kernel_launch(void* const* d_in, const int* in_sizes, int n_in,
                              void* d_out, int out_size) {
    const float* x  = (const float*)d_in[0];
    const float* W1 = (const float*)d_in[1];
    const float* b1 = (const float*)d_in[2];
    const float* W2 = (const float*)d_in[3];
    const float* b2 = (const float*)d_in[4];
    const float* W3 = (const float*)d_in[5];
    const float* b3 = (const float*)d_in[6];
    const float* W4 = (const float*)d_in[7];
    const float* b4 = (const float*)d_in[8];
    const int*   ei = (const int*)d_in[9];
    const int* batch = (const int*)d_in[10];

    int n = in_sizes[0] / FD;
    int E = in_sizes[9] / 2;
    float* out = (float*)d_out;

    float *bufA, *bufB, *dinv, *gp;
    cudaGetSymbolAddress((void**)&bufA, d_bufA);
    cudaGetSymbolAddress((void**)&bufB, d_bufB);
    cudaGetSymbolAddress((void**)&dinv, d_dinv);
    cudaGetSymbolAddress((void**)&gp,   d_gpool);

    const int smem = (FD * FD + 32 * FD) * (int)sizeof(float);  // 80KB
    cudaFuncSetAttribute(gemm128, cudaFuncAttributeMaxDynamicSharedMemorySize, smem);

    int gemm_grid = (n + 31) / 32;

    // degrees -> dinv
    deg_init<<<(n + 255) / 256, 256>>>(dinv, n);
    deg_count<<<(E + 255) / 256, 256>>>(ei + E, dinv, E);
    deg_to_dinv<<<(n + 255) / 256, 256>>>(dinv, n);

    // layer 1
    gemm128<<<gemm_grid, 256, smem>>>(x, W1, bufA, n);
    self_loop_init<<<(n * 32 + 255) / 256, 256>>>(bufA, dinv, bufB, n);
    scatter_edges<<<(E * 32 + 255) / 256, 256>>>(bufA, ei, dinv, bufB, E);
    bias_relu<<<(n * 32 + 255) / 256, 256>>>(bufB, b1, n);

    // layer 2
    gemm128<<<gemm_grid, 256, smem>>>(bufB, W2, bufA, n);
    self_loop_init<<<(n * 32 + 255) / 256, 256>>>(bufA, dinv, bufB, n);
    scatter_edges<<<(E * 32 + 255) / 256, 256>>>(bufA, ei, dinv, bufB, E);
    bias_relu<<<(n * 32 + 255) / 256, 256>>>(bufB, b2, n);

    // global max pool
    pool_init<<<(GG * FD + 255) / 256, 256>>>(gp);
    pool_max<<<(n * FD + 255) / 256, 256>>>(bufB, batch, gp, n);

    // MLP head + log_softmax
    head<<<GG, FD>>>(gp, W3, b3, W4, b4, out);
}